// round 12
// baseline (speedup 1.0000x reference)
#include <cuda_runtime.h>
#include <cuda_bf16.h>
#include <cstdint>

// Problem shapes (fixed by dataset)
#define KK 2048   // batch/k dim
#define MM 512    // feature dim m
#define NN 64    // target dim n
#define EPSV 1e-8f
#define LMAX 32

// ---------------- scratch (static device globals; no allocation) ----------------
__device__ float g_S[KK * MM];     // logits x @ w_att
__device__ float g_soft[KK * MM];  // fallback scores_soft sink
__device__ float g_hard[MM * NN];  // fallback scores_hard sink

// ---------------- tf32 helpers ----------------------------------------------
__device__ __forceinline__ uint32_t f2tf32(float f) {
    uint32_t r;
    asm("cvt.rna.tf32.f32 %0, %1;" : "=r"(r) : "f"(f));
    return r;
}
__device__ __forceinline__ void split_tf32(float f, uint32_t& hi, uint32_t& lo) {
    hi = f2tf32(f);
    lo = f2tf32(f - __uint_as_float(hi));
}
__device__ __forceinline__ void mma_tf32(float& c0, float& c1, float& c2, float& c3,
                                         uint32_t a0, uint32_t a1, uint32_t a2, uint32_t a3,
                                         uint32_t b0, uint32_t b1) {
    asm volatile(
        "mma.sync.aligned.m16n8k8.row.col.f32.tf32.tf32.f32 "
        "{%0,%1,%2,%3}, {%4,%5,%6,%7}, {%8,%9}, {%0,%1,%2,%3};"
        : "+f"(c0), "+f"(c1), "+f"(c2), "+f"(c3)
        : "r"(a0), "r"(a1), "r"(a2), "r"(a3), "r"(b0), "r"(b1));
}

// ---------------- Kernel 1: 2-split TF32 tensor-core GEMM -------------------
// S[KK,MM] = x[KK,512] @ w_att[512,MM].  Block tile 64x64, BK=16.
// 8 warps: wm = (w>>1)*16, wn = (w&1)*32; warp tile 16x32 (4 n-tiles of m16n8k8).
#define BM 64
#define BN 64
#define BK 16
#define AS_STRIDE 20
#define BS_STRIDE 72
__global__ __launch_bounds__(256) void gemm_kernel(const float* __restrict__ A,
                                                   const float* __restrict__ B) {
    __shared__ float As[BM][AS_STRIDE];   // (m, k) row-major, pad 4
    __shared__ float Bs[BK][BS_STRIDE];   // (k, n), stride 72 for conflict-free frags

    const int t    = threadIdx.x;
    const int w    = t >> 5;
    const int lane = t & 31;
    const int gid  = lane >> 2;   // 0..7
    const int tig  = lane & 3;    // 0..3
    const int wm   = (w >> 1) * 16;
    const int wn   = (w & 1) * 32;
    const int bm   = blockIdx.y * BM;
    const int bn   = blockIdx.x * BN;

    // global-load mappings (one float4 each per chunk)
    const int arow = t >> 2;           // 0..63
    const int ac4  = (t & 3) << 2;     // 0,4,8,12
    const int brow = t >> 4;           // 0..15 (k)
    const int bc4  = (t & 15) << 2;    // 0..60 (n)

    float acc[4][4];
#pragma unroll
    for (int i = 0; i < 4; i++)
#pragma unroll
        for (int j = 0; j < 4; j++) acc[i][j] = 0.f;

    // prefetch chunk 0
    float4 av = *(const float4*)&A[(size_t)(bm + arow) * MM + ac4];
    float4 bv = *(const float4*)&B[(size_t)brow * MM + bn + bc4];

    for (int kt = 0; kt < MM; kt += BK) {
        *(float4*)&As[arow][ac4] = av;
        *(float4*)&Bs[brow][bc4] = bv;
        __syncthreads();

        if (kt + BK < MM) {
            av = *(const float4*)&A[(size_t)(bm + arow) * MM + kt + BK + ac4];
            bv = *(const float4*)&B[(size_t)(kt + BK + brow) * MM + bn + bc4];
        }

#pragma unroll
        for (int ks = 0; ks < 2; ks++) {
            const int k0 = ks * 8;
            // A fragment (16x8)
            uint32_t ah[4], al[4];
            split_tf32(As[wm + gid][k0 + tig],          ah[0], al[0]);
            split_tf32(As[wm + gid + 8][k0 + tig],      ah[1], al[1]);
            split_tf32(As[wm + gid][k0 + tig + 4],      ah[2], al[2]);
            split_tf32(As[wm + gid + 8][k0 + tig + 4],  ah[3], al[3]);

#pragma unroll
            for (int nt = 0; nt < 4; nt++) {
                const int n = wn + nt * 8 + gid;
                uint32_t bh0, bl0, bh1, bl1;
                split_tf32(Bs[k0 + tig][n],     bh0, bl0);
                split_tf32(Bs[k0 + tig + 4][n], bh1, bl1);

                // small cross terms first, then main term
                mma_tf32(acc[nt][0], acc[nt][1], acc[nt][2], acc[nt][3],
                         ah[0], ah[1], ah[2], ah[3], bl0, bl1);
                mma_tf32(acc[nt][0], acc[nt][1], acc[nt][2], acc[nt][3],
                         al[0], al[1], al[2], al[3], bh0, bh1);
                mma_tf32(acc[nt][0], acc[nt][1], acc[nt][2], acc[nt][3],
                         ah[0], ah[1], ah[2], ah[3], bh0, bh1);
            }
        }
        __syncthreads();
    }

    // store C: c0,c1 at (row, col), (row, col+1); c2,c3 at (row+8, col)
    const int row = bm + wm + gid;
#pragma unroll
    for (int nt = 0; nt < 4; nt++) {
        const int col = bn + wn + nt * 8 + tig * 2;
        *(float2*)&g_S[(size_t)row * MM + col] =
            make_float2(acc[nt][0], acc[nt][1]);
        *(float2*)&g_S[(size_t)(row + 8) * MM + col] =
            make_float2(acc[nt][2], acc[nt][3]);
    }
}

// ---------------- Kernel 2: per-column top-l + hard scores  (R3-proven) -----
__global__ __launch_bounds__(32) void hard_kernel(const float* __restrict__ wb,
                                                  const int* __restrict__ lptr,
                                                  float* __restrict__ dst) {
    const int n    = blockIdx.x;
    const int lane = threadIdx.x;
    int l = lptr ? *lptr : 8;
    if (l < 1) l = 1;
    if (l > LMAX) l = LMAX;

    float v[16];
#pragma unroll
    for (int i = 0; i < 16; i++)
        v[i] = wb[(lane * 16 + i) * NN + n];

    float top[LMAX];
    for (int i = 0; i < l; i++) top[i] = -3.4e38f;
#pragma unroll
    for (int i = 0; i < 16; i++) {
        float x = v[i];
        if (x > top[l - 1]) {
            int j = l - 1;
            while (j > 0 && top[j - 1] < x) { top[j] = top[j - 1]; j--; }
            top[j] = x;
        }
    }

    int ptr = 0;
    float thr = -3.4e38f;
    for (int r = 0; r < l; r++) {
        float cand = (ptr < l) ? top[ptr] : -3.4e38f;
        float m = cand;
#pragma unroll
        for (int off = 16; off > 0; off >>= 1)
            m = fmaxf(m, __shfl_xor_sync(0xffffffffu, m, off));
        unsigned b = __ballot_sync(0xffffffffu, cand == m);
        int src = __ffs(b) - 1;
        if (lane == src) ptr++;
        thr = m;
    }

#pragma unroll
    for (int i = 0; i < 16; i++) {
        float sh = v[i] - thr + EPSV;
        sh = fminf(fmaxf(sh, -1.f), 1.f);
        float h = (sh + 1.f) * 0.5f;
        dst[(lane * 16 + i) * NN + n] = h;
    }
}

// ---------------- Kernel 3: warp-per-row softmax (R11-proven) ---------------
__global__ __launch_bounds__(256) void softmax_kernel(float* __restrict__ dst) {
    const int w    = threadIdx.x >> 5;
    const int lane = threadIdx.x & 31;
    const int k    = blockIdx.x * 8 + w;
    const float* row = g_S + (size_t)k * MM;

    float4 v[4];
#pragma unroll
    for (int j = 0; j < 4; j++)
        v[j] = __ldg((const float4*)(row + (lane << 2) + 128 * j));

    float mx = -3.4e38f;
#pragma unroll
    for (int j = 0; j < 4; j++)
        mx = fmaxf(mx, fmaxf(fmaxf(v[j].x, v[j].y), fmaxf(v[j].z, v[j].w)));
#pragma unroll
    for (int off = 16; off > 0; off >>= 1)
        mx = fmaxf(mx, __shfl_xor_sync(0xffffffffu, mx, off));

    float sum = 0.f;
#pragma unroll
    for (int j = 0; j < 4; j++) {
        v[j].x = __expf(v[j].x - mx);
        v[j].y = __expf(v[j].y - mx);
        v[j].z = __expf(v[j].z - mx);
        v[j].w = __expf(v[j].w - mx);
        sum += v[j].x + v[j].y + v[j].z + v[j].w;
    }
#pragma unroll
    for (int off = 16; off > 0; off >>= 1)
        sum += __shfl_xor_sync(0xffffffffu, sum, off);
    float inv = 1.f / sum;

    float* drow = dst + (size_t)k * MM;
#pragma unroll
    for (int j = 0; j < 4; j++) {
        float4 s = make_float4(v[j].x * inv + EPSV, v[j].y * inv + EPSV,
                               v[j].z * inv + EPSV, v[j].w * inv + EPSV);
        *(float4*)(drow + (lane << 2) + 128 * j) = s;
    }
}

// ---------------- Kernel 4: epilogue (R5-proven EXACT) ----------------------
__global__ __launch_bounds__(256) void epilogue_kernel(const float* __restrict__ x,
                                                       const float* __restrict__ soft,
                                                       const float* __restrict__ hard,
                                                       float* __restrict__ out,
                                                       float* __restrict__ mw) {
    const int idx = blockIdx.x * blockDim.x + threadIdx.x;  // 0 .. KK*MM*16-1
    const int n4  = idx & 15;
    const int km  = idx >> 4;       // 0 .. KK*MM-1
    const int m   = km & (MM - 1);

    float ss = __ldg(&soft[km]);
    float xv = __ldg(&x[km]);
    float4 h = __ldg((const float4*)(hard + m * NN + (n4 << 2)));

    float4 mw4 = make_float4(h.x * ss, h.y * ss, h.z * ss, h.w * ss);
    float4 o4  = make_float4(mw4.x * xv, mw4.y * xv, mw4.z * xv, mw4.w * xv);

    size_t base = (size_t)km * NN + (n4 << 2);
    *(float4*)&out[base] = o4;
    if (mw) *(float4*)&mw[base] = mw4;
}

// ---------------- launch: 4 sequential kernels (R5 structure) ---------------
extern "C" void kernel_launch(void* const* d_in, const int* in_sizes, int n_in,
                              void* d_out, int out_size) {
    const float* x     = (const float*)d_in[0];
    const float* w_att = (const float*)d_in[1];
    const float* w_b   = (const float*)d_in[2];
    const int*   lptr  = (n_in > 3) ? (const int*)d_in[3] : nullptr;

    const long SZ_OUT  = (long)KK * MM * NN;
    const long SZ_HARD = (long)MM * NN;
    const long SZ_SOFT = (long)KK * MM;

    float* out_ptr = (float*)d_out;
    float* hard_dst;
    float* soft_dst;
    float* mw_ptr = nullptr;
    if ((long)out_size >= SZ_OUT + SZ_HARD + SZ_SOFT + SZ_OUT) {
        hard_dst = out_ptr + SZ_OUT;
        soft_dst = hard_dst + SZ_HARD;
        mw_ptr   = soft_dst + SZ_SOFT;
    } else {
        float* dummy;
        cudaGetSymbolAddress((void**)&dummy, g_hard);
        hard_dst = dummy;
        cudaGetSymbolAddress((void**)&dummy, g_soft);
        soft_dst = dummy;
    }

    hard_kernel<<<NN, 32>>>(w_b, lptr, hard_dst);

    dim3 ggrid(MM / BN, KK / BM);
    gemm_kernel<<<ggrid, 256>>>(x, w_att);

    softmax_kernel<<<KK / 8, 256>>>(soft_dst);

    epilogue_kernel<<<(KK * MM * 16) / 256, 256>>>(x, soft_dst, hard_dst,
                                                   out_ptr, mw_ptr);
}